// round 9
// baseline (speedup 1.0000x reference)
#include <cuda_runtime.h>
#include <cuda_bf16.h>
#include <math.h>
#include <stdint.h>

static constexpr int B_   = 64;
static constexpr int HENC = 512;
static constexpr int E_   = 512;
static constexpr int H_   = 1024;
static constexpr int V_   = 32000;
static constexpr int T_   = 64;
static constexpr int SOS  = 1;
static constexpr int EOS  = 2;
static constexpr int CAND_CAP = 2048;

// ---------------- persistent device state ----------------
__device__ float g_flat[B_ * 2 * HENC];
__device__ float g_h[B_ * H_];
__device__ float g_Gc[B_ * 3 * H_];          // [64][3072] context part of gi (incl b_ih)
__device__ float g_GcT[3 * H_ * B_];         // [3072][64] transposed addend
__device__ float g_giT[3 * H_ * B_];         // [3072][64]
__device__ float g_ghT[3 * H_ * B_];
__device__ int   g_inp[B_];
__device__ int   g_fin[B_];
__device__ float g_hnorm[2];                 // {||h||_F^2, ||h - h_hi||_F^2}
__device__ unsigned g_nmax[2];               // {max ||Wh_row||, max ||Wl_row||} float bits
__device__ float g_applog[(size_t)B_ * V_]; // approx logits [batch][vocab]

// bf16 split weights / activations
__device__ __nv_bfloat16 g_WihE_hi[3 * H_ * E_];
__device__ __nv_bfloat16 g_WihE_lo[3 * H_ * E_];
__device__ __nv_bfloat16 g_Whh_hi[3 * H_ * H_];
__device__ __nv_bfloat16 g_Whh_lo[3 * H_ * H_];
__device__ __nv_bfloat16 g_Wout_hi[(size_t)V_ * H_];
__device__ __nv_bfloat16 g_x_hi[B_ * E_];
__device__ __nv_bfloat16 g_x_lo[B_ * E_];
__device__ __nv_bfloat16 g_h_hi[B_ * H_];
__device__ __nv_bfloat16 g_h_lo[B_ * H_];

// ---------------------------------------------------------------------------
__device__ __forceinline__ uint32_t smem_u32(const void* p) {
    uint32_t a;
    asm("{ .reg .u64 t; cvta.to.shared.u64 t, %1; cvt.u32.u64 %0, t; }"
        : "=r"(a) : "l"(p));
    return a;
}

#define CP16(dst, src)                                                        \
    asm volatile("cp.async.cg.shared.global [%0], [%1], 16;"                  \
                 :: "r"(dst), "l"(src))
#define CP_COMMIT() asm volatile("cp.async.commit_group;")
#define CP_WAIT(n)  asm volatile("cp.async.wait_group %0;" :: "n"(n))

#define LDMX4(R0, R1, R2, R3, ADDR)                                           \
    asm volatile("ldmatrix.sync.aligned.m8n8.x4.shared.b16 {%0,%1,%2,%3}, [%4];" \
                 : "=r"(R0), "=r"(R1), "=r"(R2), "=r"(R3) : "r"(ADDR))

#define MMA16816(D, A, Bv)                                                    \
    asm volatile("mma.sync.aligned.m16n8k16.row.col.f32.bf16.bf16.f32 "       \
                 "{%0,%1,%2,%3},{%4,%5,%6,%7},{%8,%9},{%0,%1,%2,%3};"          \
                 : "+f"(D[0]), "+f"(D[1]), "+f"(D[2]), "+f"(D[3])              \
                 : "r"(A[0]), "r"(A[1]), "r"(A[2]), "r"(A[3]),                 \
                   "r"(Bv[0]), "r"(Bv[1]))

__device__ __forceinline__ unsigned long long packkey(float v, int row) {
    unsigned ub = __float_as_uint(v);
    ub = (ub & 0x80000000u) ? ~ub : (ub | 0x80000000u);
    return ((unsigned long long)ub << 32) | (unsigned)(0xFFFFFFFFu - (unsigned)row);
}

// ---------------------------------------------------------------------------
static constexpr int SROW = 40;
__device__ __forceinline__ uint32_t abuf_off(int SPLITS, int buf, int split) {
    return (uint32_t)(buf * (SPLITS * 10240) + split * 10240);
}
__device__ __forceinline__ uint32_t bbuf_off(int SPLITS, int buf, int split) {
    return (uint32_t)(SPLITS * 20480 + buf * (SPLITS * 5120) + split * 5120);
}
static constexpr int TCSMEM2 = 61440;   // SPLITS=2 (gates)
static constexpr int TCSMEM1 = 30720;   // SPLITS=1 (logits)

// ---------------------------------------------------------------------------
// Core GEMM: D = A[M,K] @ B[64,K]^T, 128x64 tile/CTA, 8 warps, cp.async 2-stage
// SPLITS=2: 3-product bf16 split (hh+hl+lh);  SPLITS=1: hi-only.
// MODE 0: D[r*64+c] = acc + bias[r] + addT[r*64+c]
// MODE 2: g_applog[c*V + r] = acc + bias[r]
// ---------------------------------------------------------------------------
template <int MODE, int SPLITS>
__device__ __forceinline__ void mma_core(
    const __nv_bfloat16* __restrict__ Ah, const __nv_bfloat16* __restrict__ Al,
    const __nv_bfloat16* __restrict__ Bh, const __nv_bfloat16* __restrict__ Bl,
    int K, const float* __restrict__ bias, const float* __restrict__ addT,
    float* __restrict__ D, int m0)
{
    extern __shared__ __align__(16) char smem[];
    const uint32_t sb = smem_u32(smem);
    const int tid = threadIdx.x, lane = tid & 31, warp = tid >> 5;
    const int mw = warp * 16;

    float acc[8][4];
#pragma unroll
    for (int f = 0; f < 8; f++)
#pragma unroll
        for (int j = 0; j < 4; j++) acc[f][j] = 0.f;

    const int a_row  = mw + ((lane >> 3) & 1) * 8 + (lane & 7);
    const int a_koff = (lane >> 4) * 8;
    const int b_row  = (lane >> 4) * 8 + (lane & 7);
    const int b_koff = ((lane >> 3) & 1) * 8;

    const int nch = K >> 5;

    auto stage = [&](int kc, int buf) {
        const int kb = kc << 5;
#pragma unroll
        for (int i = 0; i < 2; i++) {
            int id = tid + (i << 8);
            int r = id >> 2, c = id & 3;
            uint32_t so = (uint32_t)(r * 80 + c * 16);
            const size_t go = (size_t)(m0 + r) * K + kb + c * 8;
            CP16(sb + abuf_off(SPLITS, buf, 0) + so, Ah + go);
            if (SPLITS == 2) CP16(sb + abuf_off(SPLITS, buf, 1) + so, Al + go);
        }
        {
            int r = tid >> 2, c = tid & 3;
            uint32_t so = (uint32_t)(r * 80 + c * 16);
            const size_t go = (size_t)r * K + kb + c * 8;
            CP16(sb + bbuf_off(SPLITS, buf, 0) + so, Bh + go);
            if (SPLITS == 2) CP16(sb + bbuf_off(SPLITS, buf, 1) + so, Bl + go);
        }
    };

    stage(0, 0);
    CP_COMMIT();

    for (int kc = 0; kc < nch; kc++) {
        const int cur = kc & 1;
        if (kc + 1 < nch) {
            stage(kc + 1, cur ^ 1);
            CP_COMMIT();
            CP_WAIT(1);
        } else {
            CP_WAIT(0);
        }
        __syncthreads();

#pragma unroll
        for (int ks = 0; ks < 2; ks++) {
            const int kk = ks * 16;
            uint32_t ah[4], al[4];
            {
                uint32_t ad = sb + abuf_off(SPLITS, cur, 0) +
                              (uint32_t)((a_row * SROW + kk + a_koff) * 2);
                LDMX4(ah[0], ah[1], ah[2], ah[3], ad);
                if (SPLITS == 2) {
                    ad = sb + abuf_off(SPLITS, cur, 1) +
                         (uint32_t)((a_row * SROW + kk + a_koff) * 2);
                    LDMX4(al[0], al[1], al[2], al[3], ad);
                }
            }
            uint32_t bh[8][2], bl[8][2];
#pragma unroll
            for (int p = 0; p < 4; p++) {
                uint32_t ad = sb + bbuf_off(SPLITS, cur, 0) +
                              (uint32_t)(((p * 16 + b_row) * SROW + kk + b_koff) * 2);
                LDMX4(bh[2 * p][0], bh[2 * p][1], bh[2 * p + 1][0], bh[2 * p + 1][1], ad);
                if (SPLITS == 2) {
                    ad = sb + bbuf_off(SPLITS, cur, 1) +
                         (uint32_t)(((p * 16 + b_row) * SROW + kk + b_koff) * 2);
                    LDMX4(bl[2 * p][0], bl[2 * p][1], bl[2 * p + 1][0], bl[2 * p + 1][1], ad);
                }
            }
#pragma unroll
            for (int f = 0; f < 8; f++) {
                MMA16816(acc[f], ah, bh[f]);
                if (SPLITS == 2) {
                    MMA16816(acc[f], ah, bl[f]);
                    MMA16816(acc[f], al, bh[f]);
                }
            }
        }
        __syncthreads();
    }

    const int g  = lane >> 2;
    const int tq = lane & 3;
    const int r0 = m0 + mw + g;
    const int r1 = r0 + 8;
    const float b0v = bias ? bias[r0] : 0.f;
    const float b1v = bias ? bias[r1] : 0.f;

    if (MODE == 0) {
#pragma unroll
        for (int f = 0; f < 8; f++) {
#pragma unroll
            for (int j = 0; j < 2; j++) {
                const int c = f * 8 + tq * 2 + j;
                float v0 = acc[f][j]     + b0v;
                float v1 = acc[f][2 + j] + b1v;
                if (addT) {
                    v0 += addT[(size_t)r0 * 64 + c];
                    v1 += addT[(size_t)r1 * 64 + c];
                }
                D[(size_t)r0 * 64 + c] = v0;
                D[(size_t)r1 * 64 + c] = v1;
            }
        }
    } else {
#pragma unroll
        for (int f = 0; f < 8; f++) {
#pragma unroll
            for (int j = 0; j < 2; j++) {
                const int c = f * 8 + tq * 2 + j;
                g_applog[(size_t)c * V_ + r0] = acc[f][j]     + b0v;
                g_applog[(size_t)c * V_ + r1] = acc[f][2 + j] + b1v;
            }
        }
    }
}

__global__ void __launch_bounds__(256) k_tc_gates(const float* __restrict__ b_hh) {
    const int m0 = blockIdx.x * 128;
    if (blockIdx.y == 0)
        mma_core<0, 2>(g_WihE_hi, g_WihE_lo, g_x_hi, g_x_lo, E_,
                       nullptr, g_GcT, g_giT, m0);
    else
        mma_core<0, 2>(g_Whh_hi, g_Whh_lo, g_h_hi, g_h_lo, H_,
                       b_hh, nullptr, g_ghT, m0);
}

__global__ void __launch_bounds__(256) k_tc_logits(const float* __restrict__ out_b) {
    mma_core<2, 1>(g_Wout_hi, nullptr, g_h_hi, nullptr, H_,
                   out_b, nullptr, nullptr, blockIdx.x * 128);
}

// ---------------------------------------------------------------------------
__global__ void k_setup(const float* __restrict__ enc) {
    int idx = blockIdx.x * blockDim.x + threadIdx.x;
    if (idx < B_ * 2 * HENC) {
        int b = idx / (2 * HENC);
        int k = idx % (2 * HENC);
        float v = (k < HENC) ? enc[b * HENC + k]
                             : enc[B_ * HENC + b * HENC + (k - HENC)];
        g_flat[idx] = v;
    }
    if (idx < B_) { g_inp[idx] = SOS; g_fin[idx] = 0; }
    if (idx < 2)  { g_nmax[idx] = 0u; }
}

__global__ void __launch_bounds__(256) k_gemm(
    const float* __restrict__ A, int lda,
    const float* __restrict__ W, int ldw, int woff, int K,
    const float* __restrict__ bias, float* __restrict__ C, int ldc)
{
    __shared__ float As[32][68];
    __shared__ float Ws[32][68];
    const int tid = threadIdx.x;
    const int tx = tid & 15, ty = tid >> 4;
    const int n0 = blockIdx.x * 64;
    float acc[4][4] = {};

    for (int k0 = 0; k0 < K; k0 += 32) {
#pragma unroll
        for (int it = 0; it < 2; it++) {
            int idx = tid + it * 256;
            int row = idx >> 3;
            int kq  = (idx & 7) << 2;
            float4 v = *(const float4*)(A + (size_t)row * lda + k0 + kq);
            As[kq][row] = v.x; As[kq + 1][row] = v.y;
            As[kq + 2][row] = v.z; As[kq + 3][row] = v.w;
            float4 u = *(const float4*)(W + (size_t)(n0 + row) * ldw + woff + k0 + kq);
            Ws[kq][row] = u.x; Ws[kq + 1][row] = u.y;
            Ws[kq + 2][row] = u.z; Ws[kq + 3][row] = u.w;
        }
        __syncthreads();
#pragma unroll
        for (int k = 0; k < 32; k++) {
            float4 a = *(const float4*)&As[k][ty << 2];
            float4 w = *(const float4*)&Ws[k][tx << 2];
            acc[0][0] += a.x * w.x; acc[0][1] += a.x * w.y; acc[0][2] += a.x * w.z; acc[0][3] += a.x * w.w;
            acc[1][0] += a.y * w.x; acc[1][1] += a.y * w.y; acc[1][2] += a.y * w.z; acc[1][3] += a.y * w.w;
            acc[2][0] += a.z * w.x; acc[2][1] += a.z * w.y; acc[2][2] += a.z * w.z; acc[2][3] += a.z * w.w;
            acc[3][0] += a.w * w.x; acc[3][1] += a.w * w.y; acc[3][2] += a.w * w.z; acc[3][3] += a.w * w.w;
        }
        __syncthreads();
    }
#pragma unroll
    for (int i = 0; i < 4; i++) {
        int row = (ty << 2) + i;
#pragma unroll
        for (int j = 0; j < 4; j++) {
            int col = n0 + (tx << 2) + j;
            float v = acc[i][j];
            if (bias) v += bias[col];
            C[(size_t)row * ldc + col] = v;
        }
    }
}

__global__ void k_splitw(const float* __restrict__ src, int ld, int coloff, int cols,
                         __nv_bfloat16* __restrict__ hi, __nv_bfloat16* __restrict__ lo,
                         int n)
{
    int idx = blockIdx.x * blockDim.x + threadIdx.x;
    if (idx >= n) return;
    int r = idx / cols, c = idx % cols;
    float v = src[(size_t)r * ld + coloff + c];
    __nv_bfloat16 h = __float2bfloat16(v);
    hi[idx] = h;
    if (lo) lo[idx] = __float2bfloat16(v - __bfloat162float(h));
}

__global__ void k_split_h0() {
    int idx = blockIdx.x * blockDim.x + threadIdx.x;
    if (idx >= B_ * H_) return;
    float v = g_h[idx];
    __nv_bfloat16 h = __float2bfloat16(v);
    g_h_hi[idx] = h;
    g_h_lo[idx] = __float2bfloat16(v - __bfloat162float(h));
}

__global__ void k_mk_gcT() {
    int idx = blockIdx.x * blockDim.x + threadIdx.x;
    if (idx >= 3 * H_ * B_) return;
    int r = idx >> 6, c = idx & 63;
    g_GcT[idx] = g_Gc[(size_t)c * (3 * H_) + r];
}

__global__ void k_wnorms(const float* __restrict__ out_w) {
    int r = blockIdx.x * 8 + (threadIdx.x >> 5);
    int lane = threadIdx.x & 31;
    if (r >= V_) return;
    float sh = 0.f, sl = 0.f;
    for (int k = lane; k < H_; k += 32) {
        float w  = out_w[(size_t)r * H_ + k];
        float wh = __bfloat162float(g_Wout_hi[(size_t)r * H_ + k]);
        float wl = w - wh;
        sh += wh * wh;
        sl += wl * wl;
    }
#pragma unroll
    for (int s = 16; s > 0; s >>= 1) {
        sh += __shfl_xor_sync(0xffffffffu, sh, s);
        sl += __shfl_xor_sync(0xffffffffu, sl, s);
    }
    if (lane == 0) {
        atomicMax(&g_nmax[0], __float_as_uint(sqrtf(sh)));
        atomicMax(&g_nmax[1], __float_as_uint(sqrtf(sl)));
    }
}

__global__ void k_split_x(const float* __restrict__ emb) {
    int idx = blockIdx.x * blockDim.x + threadIdx.x;
    if (idx < 2) g_hnorm[idx] = 0.f;
    if (idx >= B_ * E_) return;
    int b = idx >> 9;
    int k = idx & (E_ - 1);
    float v = emb[(size_t)g_inp[b] * E_ + k];
    __nv_bfloat16 h = __float2bfloat16(v);
    g_x_hi[idx] = h;
    g_x_lo[idx] = __float2bfloat16(v - __bfloat162float(h));
}

__global__ void __launch_bounds__(256) k_gates2() {
    __shared__ float s1[256], s2[256];
    int tid = threadIdx.x;
    int idx = blockIdx.x * 256 + tid;
    int b = idx & (B_ - 1);
    int i = idx >> 6;
    float ir  = g_giT[(size_t)i * 64 + b];
    float iz  = g_giT[(size_t)(H_ + i) * 64 + b];
    float in_ = g_giT[(size_t)(2 * H_ + i) * 64 + b];
    float hr  = g_ghT[(size_t)i * 64 + b];
    float hz  = g_ghT[(size_t)(H_ + i) * 64 + b];
    float hn  = g_ghT[(size_t)(2 * H_ + i) * 64 + b];
    float r = 1.f / (1.f + expf(-(ir + hr)));
    float z = 1.f / (1.f + expf(-(iz + hz)));
    float n = tanhf(in_ + r * hn);
    size_t hidx = (size_t)b * H_ + i;
    float h = g_h[hidx];
    float hnew = (1.f - z) * n + z * h;
    g_h[hidx] = hnew;
    __nv_bfloat16 hh = __float2bfloat16(hnew);
    g_h_hi[hidx] = hh;
    float hif = __bfloat162float(hh);
    g_h_lo[hidx] = __float2bfloat16(hnew - hif);
    float res = hnew - hif;
    s1[tid] = hnew * hnew;
    s2[tid] = res * res;
    __syncthreads();
#pragma unroll
    for (int s = 128; s > 0; s >>= 1) {
        if (tid < s) { s1[tid] += s1[tid + s]; s2[tid] += s2[tid + s]; }
        __syncthreads();
    }
    if (tid == 0) {
        atomicAdd(&g_hnorm[0], s1[0]);
        atomicAdd(&g_hnorm[1], s2[0]);
    }
}

// ---------------------------------------------------------------------------
// Rescore with inflated margin + guaranteed full-scan fallback on overflow.
// ---------------------------------------------------------------------------
__global__ void __launch_bounds__(256) k_rescore(
    const float* __restrict__ out_w, const float* __restrict__ out_b,
    float* __restrict__ out_tok, int t)
{
    __shared__ float sh_h[H_];
    __shared__ int cand[CAND_CAP];
    __shared__ int cnt;
    __shared__ float smax[8];
    __shared__ unsigned long long bestkey;

    const int b = blockIdx.x;
    const int tid = threadIdx.x, lane = tid & 31, warp = tid >> 5;
    const float* ap = g_applog + (size_t)b * V_;

    for (int i = tid; i < H_; i += 256) sh_h[i] = g_h[(size_t)b * H_ + i];
    if (tid == 0) { cnt = 0; bestkey = 0ULL; }
    __syncthreads();

    // pass A: max of approx logits
    float mx = -1e30f;
    for (int r = tid; r < V_; r += 256) mx = fmaxf(mx, ap[r]);
#pragma unroll
    for (int s = 16; s > 0; s >>= 1)
        mx = fmaxf(mx, __shfl_xor_sync(0xffffffffu, mx, s));
    if (lane == 0) smax[warp] = mx;
    __syncthreads();
    if (tid == 0) {
        float m = smax[0];
#pragma unroll
        for (int w = 1; w < 8; w++) m = fmaxf(m, smax[w]);
        smax[0] = m;
    }
    __syncthreads();
    const float A = smax[0];

    const float nh  = sqrtf(g_hnorm[0]);
    const float nhl = sqrtf(g_hnorm[1]);
    const float nwh = __uint_as_float(g_nmax[0]);
    const float nwl = __uint_as_float(g_nmax[1]);
    const float eps = 4.f * (nwl * nh + nwh * nhl) + 0.25f;   // inflated margin
    const float thresh = A - eps;

    // pass B: candidates
    for (int r = tid; r < V_; r += 256) {
        if (ap[r] >= thresh) {
            int i = atomicAdd(&cnt, 1);
            if (i < CAND_CAP) cand[i] = r;
        }
    }
    __syncthreads();

    if (cnt <= CAND_CAP) {
        const int nc = cnt;
        for (int ci = warp; ci < nc; ci += 8) {
            const int r = cand[ci];
            float s = 0.f;
            for (int k = lane; k < H_; k += 32)
                s += out_w[(size_t)r * H_ + k] * sh_h[k];
#pragma unroll
            for (int sft = 16; sft > 0; sft >>= 1)
                s += __shfl_xor_sync(0xffffffffu, s, sft);
            if (lane == 0)
                atomicMax(&bestkey, packkey(s + out_b[r], r));
        }
    } else {
        // overflow: exact full scan — correctness independent of the bound
        for (int r = warp; r < V_; r += 8) {
            float s = 0.f;
            for (int k = lane; k < H_; k += 32)
                s += out_w[(size_t)r * H_ + k] * sh_h[k];
#pragma unroll
            for (int sft = 16; sft > 0; sft >>= 1)
                s += __shfl_xor_sync(0xffffffffu, s, sft);
            if (lane == 0)
                atomicMax(&bestkey, packkey(s + out_b[r], r));
        }
    }
    __syncthreads();

    if (tid == 0) {
        int tok = (int)(0xFFFFFFFFu - (unsigned)(bestkey & 0xFFFFFFFFull));
        out_tok[b * T_ + t] = (float)tok;
        int fin = g_fin[b] | (tok == EOS);
        g_fin[b] = fin;
        g_inp[b] = fin ? EOS : tok;
    }
}

__global__ void k_writeh(float* __restrict__ out_h) {
    int idx = blockIdx.x * blockDim.x + threadIdx.x;
    if (idx < B_ * H_) out_h[idx] = g_h[idx];
}

// ---------------------------------------------------------------------------
extern "C" void kernel_launch(void* const* d_in, const int* in_sizes, int n_in,
                              void* d_out, int out_size) {
    const float* enc   = (const float*)d_in[0];
    const float* emb   = (const float*)d_in[1];
    const float* Wh_w  = (const float*)d_in[2];
    const float* Wh_b  = (const float*)d_in[3];
    const float* W_ih  = (const float*)d_in[4];
    const float* W_hh  = (const float*)d_in[5];
    const float* b_ih  = (const float*)d_in[6];
    const float* b_hh  = (const float*)d_in[7];
    const float* out_w = (const float*)d_in[8];
    const float* out_b = (const float*)d_in[9];
    float* out = (float*)d_out;

    void* pv;
    cudaGetSymbolAddress(&pv, g_flat);     float* f_flat = (float*)pv;
    cudaGetSymbolAddress(&pv, g_h);        float* f_h    = (float*)pv;
    cudaGetSymbolAddress(&pv, g_Gc);       float* f_Gc   = (float*)pv;
    cudaGetSymbolAddress(&pv, g_WihE_hi);  __nv_bfloat16* w_ihe_h = (__nv_bfloat16*)pv;
    cudaGetSymbolAddress(&pv, g_WihE_lo);  __nv_bfloat16* w_ihe_l = (__nv_bfloat16*)pv;
    cudaGetSymbolAddress(&pv, g_Whh_hi);   __nv_bfloat16* w_hh_h  = (__nv_bfloat16*)pv;
    cudaGetSymbolAddress(&pv, g_Whh_lo);   __nv_bfloat16* w_hh_l  = (__nv_bfloat16*)pv;
    cudaGetSymbolAddress(&pv, g_Wout_hi);  __nv_bfloat16* w_o_h   = (__nv_bfloat16*)pv;

    cudaFuncSetAttribute(k_tc_gates,  cudaFuncAttributeMaxDynamicSharedMemorySize, TCSMEM2);
    cudaFuncSetAttribute(k_tc_logits, cudaFuncAttributeMaxDynamicSharedMemorySize, TCSMEM1);

    // ---- one-time setup ----
    k_setup<<<256, 256>>>(enc);
    k_gemm<<<H_ / 64, 256>>>(f_flat, 2 * HENC, Wh_w, 2 * HENC, 0, 2 * HENC, Wh_b, f_h, H_);
    k_gemm<<<3 * H_ / 64, 256>>>(f_flat, 2 * HENC, W_ih, E_ + 2 * HENC, E_, 2 * HENC,
                                 b_ih, f_Gc, 3 * H_);
    k_split_h0<<<(B_ * H_) / 256, 256>>>();
    k_mk_gcT<<<(3 * H_ * B_) / 256, 256>>>();
    k_splitw<<<(3 * H_ * E_) / 256, 256>>>(W_ih, E_ + 2 * HENC, 0, E_,
                                           w_ihe_h, w_ihe_l, 3 * H_ * E_);
    k_splitw<<<(3 * H_ * H_) / 256, 256>>>(W_hh, H_, 0, H_,
                                           w_hh_h, w_hh_l, 3 * H_ * H_);
    k_splitw<<<(V_ * H_) / 256, 256>>>(out_w, H_, 0, H_,
                                       w_o_h, nullptr, V_ * H_);
    k_wnorms<<<V_ / 8, 256>>>(out_w);

    // ---- decode loop ----
    dim3 ggates(3 * H_ / 128, 2);
    for (int t = 0; t < T_; t++) {
        k_split_x<<<(B_ * E_) / 256, 256>>>(emb);
        k_tc_gates<<<ggates, 256, TCSMEM2>>>(b_hh);
        k_gates2<<<(B_ * H_) / 256, 256>>>();
        k_tc_logits<<<V_ / 128, 256, TCSMEM1>>>(out_b);
        k_rescore<<<B_, 256>>>(out_w, out_b, out, t);
    }

    if (out_size >= B_ * T_ + B_ * H_)
        k_writeh<<<(B_ * H_) / 256, 256>>>(out + B_ * T_);
}

// round 10
// speedup vs baseline: 57.5699x; 57.5699x over previous
#include <cuda_runtime.h>
#include <cuda_bf16.h>
#include <math.h>
#include <stdint.h>

static constexpr int B_   = 64;
static constexpr int HENC = 512;
static constexpr int E_   = 512;
static constexpr int H_   = 1024;
static constexpr int V_   = 32000;
static constexpr int T_   = 64;
static constexpr int SOS  = 1;
static constexpr int EOS  = 2;
static constexpr int CAND_CAP = 2048;

// ---------------- persistent device state ----------------
__device__ float g_flat[B_ * 2 * HENC];
__device__ float g_h[B_ * H_];
__device__ float g_Gc[B_ * 3 * H_];
__device__ float g_GcT[3 * H_ * B_];
__device__ float g_giT[3 * H_ * B_];
__device__ float g_ghT[3 * H_ * B_];
__device__ int   g_inp[B_];
__device__ int   g_fin[B_];
__device__ float g_hnorm[2 * B_];            // per-batch {‖h_b‖², ‖h_b−h_hi‖²}
__device__ unsigned g_nmax[2];               // {max ‖Wh_row‖, max ‖Wl_row‖} float bits
__device__ float g_applog[(size_t)B_ * V_];  // approx logits [batch][vocab]

// bf16 split weights / activations
__device__ __nv_bfloat16 g_WihE_hi[3 * H_ * E_];
__device__ __nv_bfloat16 g_WihE_lo[3 * H_ * E_];
__device__ __nv_bfloat16 g_Whh_hi[3 * H_ * H_];
__device__ __nv_bfloat16 g_Whh_lo[3 * H_ * H_];
__device__ __nv_bfloat16 g_Wout_hi[(size_t)V_ * H_];
__device__ __nv_bfloat16 g_x_hi[B_ * E_];
__device__ __nv_bfloat16 g_x_lo[B_ * E_];
__device__ __nv_bfloat16 g_h_hi[B_ * H_];
__device__ __nv_bfloat16 g_h_lo[B_ * H_];

// ---------------------------------------------------------------------------
__device__ __forceinline__ uint32_t smem_u32(const void* p) {
    uint32_t a;
    asm("{ .reg .u64 t; cvta.to.shared.u64 t, %1; cvt.u32.u64 %0, t; }"
        : "=r"(a) : "l"(p));
    return a;
}

#define CP16(dst, src)                                                        \
    asm volatile("cp.async.cg.shared.global [%0], [%1], 16;"                  \
                 :: "r"(dst), "l"(src))
#define CP_COMMIT() asm volatile("cp.async.commit_group;")
#define CP_WAIT(n)  asm volatile("cp.async.wait_group %0;" :: "n"(n))

#define LDMX4(R0, R1, R2, R3, ADDR)                                           \
    asm volatile("ldmatrix.sync.aligned.m8n8.x4.shared.b16 {%0,%1,%2,%3}, [%4];" \
                 : "=r"(R0), "=r"(R1), "=r"(R2), "=r"(R3) : "r"(ADDR))

#define MMA16816(D, A, Bv)                                                    \
    asm volatile("mma.sync.aligned.m16n8k16.row.col.f32.bf16.bf16.f32 "       \
                 "{%0,%1,%2,%3},{%4,%5,%6,%7},{%8,%9},{%0,%1,%2,%3};"          \
                 : "+f"(D[0]), "+f"(D[1]), "+f"(D[2]), "+f"(D[3])              \
                 : "r"(A[0]), "r"(A[1]), "r"(A[2]), "r"(A[3]),                 \
                   "r"(Bv[0]), "r"(Bv[1]))

__device__ __forceinline__ unsigned long long packkey(float v, int row) {
    unsigned ub = __float_as_uint(v);
    ub = (ub & 0x80000000u) ? ~ub : (ub | 0x80000000u);
    return ((unsigned long long)ub << 32) | (unsigned)(0xFFFFFFFFu - (unsigned)row);
}

// ---------------------------------------------------------------------------
static constexpr int SROW = 40;
__device__ __forceinline__ uint32_t abuf_off(int SPLITS, int buf, int split) {
    return (uint32_t)(buf * (SPLITS * 10240) + split * 10240);
}
__device__ __forceinline__ uint32_t bbuf_off(int SPLITS, int buf, int split) {
    return (uint32_t)(SPLITS * 20480 + buf * (SPLITS * 5120) + split * 5120);
}
static constexpr int TCSMEM2 = 61440;   // SPLITS=2 (gates)
static constexpr int TCSMEM1 = 30720;   // SPLITS=1 (logits)

// ---------------------------------------------------------------------------
// Core GEMM: D = A[M,K] @ B[64,K]^T, 128x64 tile/CTA, 8 warps, cp.async 2-stage
// SPLITS=2: 3-product bf16 split (hh+hl+lh);  SPLITS=1: hi-only.
// MODE 0: D[r*64+c] = acc + bias[r] + addT[r*64+c]
// MODE 2: g_applog[c*V + r] = acc + bias[r]
// ---------------------------------------------------------------------------
template <int MODE, int SPLITS>
__device__ __forceinline__ void mma_core(
    const __nv_bfloat16* __restrict__ Ah, const __nv_bfloat16* __restrict__ Al,
    const __nv_bfloat16* __restrict__ Bh, const __nv_bfloat16* __restrict__ Bl,
    int K, const float* __restrict__ bias, const float* __restrict__ addT,
    float* __restrict__ D, int m0)
{
    extern __shared__ __align__(16) char smem[];
    const uint32_t sb = smem_u32(smem);
    const int tid = threadIdx.x, lane = tid & 31, warp = tid >> 5;
    const int mw = warp * 16;

    float acc[8][4];
#pragma unroll
    for (int f = 0; f < 8; f++)
#pragma unroll
        for (int j = 0; j < 4; j++) acc[f][j] = 0.f;

    const int a_row  = mw + ((lane >> 3) & 1) * 8 + (lane & 7);
    const int a_koff = (lane >> 4) * 8;
    const int b_row  = (lane >> 4) * 8 + (lane & 7);
    const int b_koff = ((lane >> 3) & 1) * 8;

    const int nch = K >> 5;

    auto stage = [&](int kc, int buf) {
        const int kb = kc << 5;
#pragma unroll
        for (int i = 0; i < 2; i++) {
            int id = tid + (i << 8);
            int r = id >> 2, c = id & 3;
            uint32_t so = (uint32_t)(r * 80 + c * 16);
            const size_t go = (size_t)(m0 + r) * K + kb + c * 8;
            CP16(sb + abuf_off(SPLITS, buf, 0) + so, Ah + go);
            if (SPLITS == 2) CP16(sb + abuf_off(SPLITS, buf, 1) + so, Al + go);
        }
        {
            int r = tid >> 2, c = tid & 3;
            uint32_t so = (uint32_t)(r * 80 + c * 16);
            const size_t go = (size_t)r * K + kb + c * 8;
            CP16(sb + bbuf_off(SPLITS, buf, 0) + so, Bh + go);
            if (SPLITS == 2) CP16(sb + bbuf_off(SPLITS, buf, 1) + so, Bl + go);
        }
    };

    stage(0, 0);
    CP_COMMIT();

    for (int kc = 0; kc < nch; kc++) {
        const int cur = kc & 1;
        if (kc + 1 < nch) {
            stage(kc + 1, cur ^ 1);
            CP_COMMIT();
            CP_WAIT(1);
        } else {
            CP_WAIT(0);
        }
        __syncthreads();

#pragma unroll
        for (int ks = 0; ks < 2; ks++) {
            const int kk = ks * 16;
            uint32_t ah[4], al[4];
            {
                uint32_t ad = sb + abuf_off(SPLITS, cur, 0) +
                              (uint32_t)((a_row * SROW + kk + a_koff) * 2);
                LDMX4(ah[0], ah[1], ah[2], ah[3], ad);
                if (SPLITS == 2) {
                    ad = sb + abuf_off(SPLITS, cur, 1) +
                         (uint32_t)((a_row * SROW + kk + a_koff) * 2);
                    LDMX4(al[0], al[1], al[2], al[3], ad);
                }
            }
            uint32_t bh[8][2], bl[8][2];
#pragma unroll
            for (int p = 0; p < 4; p++) {
                uint32_t ad = sb + bbuf_off(SPLITS, cur, 0) +
                              (uint32_t)(((p * 16 + b_row) * SROW + kk + b_koff) * 2);
                LDMX4(bh[2 * p][0], bh[2 * p][1], bh[2 * p + 1][0], bh[2 * p + 1][1], ad);
                if (SPLITS == 2) {
                    ad = sb + bbuf_off(SPLITS, cur, 1) +
                         (uint32_t)(((p * 16 + b_row) * SROW + kk + b_koff) * 2);
                    LDMX4(bl[2 * p][0], bl[2 * p][1], bl[2 * p + 1][0], bl[2 * p + 1][1], ad);
                }
            }
#pragma unroll
            for (int f = 0; f < 8; f++) {
                MMA16816(acc[f], ah, bh[f]);
                if (SPLITS == 2) {
                    MMA16816(acc[f], ah, bl[f]);
                    MMA16816(acc[f], al, bh[f]);
                }
            }
        }
        __syncthreads();
    }

    const int g  = lane >> 2;
    const int tq = lane & 3;
    const int r0 = m0 + mw + g;
    const int r1 = r0 + 8;
    const float b0v = bias ? bias[r0] : 0.f;
    const float b1v = bias ? bias[r1] : 0.f;

    if (MODE == 0) {
#pragma unroll
        for (int f = 0; f < 8; f++) {
#pragma unroll
            for (int j = 0; j < 2; j++) {
                const int c = f * 8 + tq * 2 + j;
                float v0 = acc[f][j]     + b0v;
                float v1 = acc[f][2 + j] + b1v;
                if (addT) {
                    v0 += addT[(size_t)r0 * 64 + c];
                    v1 += addT[(size_t)r1 * 64 + c];
                }
                D[(size_t)r0 * 64 + c] = v0;
                D[(size_t)r1 * 64 + c] = v1;
            }
        }
    } else {
#pragma unroll
        for (int f = 0; f < 8; f++) {
#pragma unroll
            for (int j = 0; j < 2; j++) {
                const int c = f * 8 + tq * 2 + j;
                g_applog[(size_t)c * V_ + r0] = acc[f][j]     + b0v;
                g_applog[(size_t)c * V_ + r1] = acc[f][2 + j] + b1v;
            }
        }
    }
}

__global__ void __launch_bounds__(256) k_tc_gates(const float* __restrict__ b_hh) {
    const int m0 = blockIdx.x * 128;
    if (blockIdx.y == 0)
        mma_core<0, 2>(g_WihE_hi, g_WihE_lo, g_x_hi, g_x_lo, E_,
                       nullptr, g_GcT, g_giT, m0);
    else
        mma_core<0, 2>(g_Whh_hi, g_Whh_lo, g_h_hi, g_h_lo, H_,
                       b_hh, nullptr, g_ghT, m0);
}

__global__ void __launch_bounds__(256) k_tc_logits(const float* __restrict__ out_b) {
    mma_core<2, 1>(g_Wout_hi, nullptr, g_h_hi, nullptr, H_,
                   out_b, nullptr, nullptr, blockIdx.x * 128);
}

// ---------------------------------------------------------------------------
__global__ void k_setup(const float* __restrict__ enc) {
    int idx = blockIdx.x * blockDim.x + threadIdx.x;
    if (idx < B_ * 2 * HENC) {
        int b = idx / (2 * HENC);
        int k = idx % (2 * HENC);
        float v = (k < HENC) ? enc[b * HENC + k]
                             : enc[B_ * HENC + b * HENC + (k - HENC)];
        g_flat[idx] = v;
    }
    if (idx < B_) { g_inp[idx] = SOS; g_fin[idx] = 0; }
    if (idx < 2)  { g_nmax[idx] = 0u; }
}

__global__ void __launch_bounds__(256) k_gemm(
    const float* __restrict__ A, int lda,
    const float* __restrict__ W, int ldw, int woff, int K,
    const float* __restrict__ bias, float* __restrict__ C, int ldc)
{
    __shared__ float As[32][68];
    __shared__ float Ws[32][68];
    const int tid = threadIdx.x;
    const int tx = tid & 15, ty = tid >> 4;
    const int n0 = blockIdx.x * 64;
    float acc[4][4] = {};

    for (int k0 = 0; k0 < K; k0 += 32) {
#pragma unroll
        for (int it = 0; it < 2; it++) {
            int idx = tid + it * 256;
            int row = idx >> 3;
            int kq  = (idx & 7) << 2;
            float4 v = *(const float4*)(A + (size_t)row * lda + k0 + kq);
            As[kq][row] = v.x; As[kq + 1][row] = v.y;
            As[kq + 2][row] = v.z; As[kq + 3][row] = v.w;
            float4 u = *(const float4*)(W + (size_t)(n0 + row) * ldw + woff + k0 + kq);
            Ws[kq][row] = u.x; Ws[kq + 1][row] = u.y;
            Ws[kq + 2][row] = u.z; Ws[kq + 3][row] = u.w;
        }
        __syncthreads();
#pragma unroll
        for (int k = 0; k < 32; k++) {
            float4 a = *(const float4*)&As[k][ty << 2];
            float4 w = *(const float4*)&Ws[k][tx << 2];
            acc[0][0] += a.x * w.x; acc[0][1] += a.x * w.y; acc[0][2] += a.x * w.z; acc[0][3] += a.x * w.w;
            acc[1][0] += a.y * w.x; acc[1][1] += a.y * w.y; acc[1][2] += a.y * w.z; acc[1][3] += a.y * w.w;
            acc[2][0] += a.z * w.x; acc[2][1] += a.z * w.y; acc[2][2] += a.z * w.z; acc[2][3] += a.z * w.w;
            acc[3][0] += a.w * w.x; acc[3][1] += a.w * w.y; acc[3][2] += a.w * w.z; acc[3][3] += a.w * w.w;
        }
        __syncthreads();
    }
#pragma unroll
    for (int i = 0; i < 4; i++) {
        int row = (ty << 2) + i;
#pragma unroll
        for (int j = 0; j < 4; j++) {
            int col = n0 + (tx << 2) + j;
            float v = acc[i][j];
            if (bias) v += bias[col];
            C[(size_t)row * ldc + col] = v;
        }
    }
}

__global__ void k_splitw(const float* __restrict__ src, int ld, int coloff, int cols,
                         __nv_bfloat16* __restrict__ hi, __nv_bfloat16* __restrict__ lo,
                         int n)
{
    int idx = blockIdx.x * blockDim.x + threadIdx.x;
    if (idx >= n) return;
    int r = idx / cols, c = idx % cols;
    float v = src[(size_t)r * ld + coloff + c];
    __nv_bfloat16 h = __float2bfloat16(v);
    hi[idx] = h;
    if (lo) lo[idx] = __float2bfloat16(v - __bfloat162float(h));
}

__global__ void k_split_h0() {
    int idx = blockIdx.x * blockDim.x + threadIdx.x;
    if (idx >= B_ * H_) return;
    float v = g_h[idx];
    __nv_bfloat16 h = __float2bfloat16(v);
    g_h_hi[idx] = h;
    g_h_lo[idx] = __float2bfloat16(v - __bfloat162float(h));
}

__global__ void k_mk_gcT() {
    int idx = blockIdx.x * blockDim.x + threadIdx.x;
    if (idx >= 3 * H_ * B_) return;
    int r = idx >> 6, c = idx & 63;
    g_GcT[idx] = g_Gc[(size_t)c * (3 * H_) + r];
}

__global__ void k_wnorms(const float* __restrict__ out_w) {
    int r = blockIdx.x * 8 + (threadIdx.x >> 5);
    int lane = threadIdx.x & 31;
    if (r >= V_) return;
    float sh = 0.f, sl = 0.f;
    for (int k = lane; k < H_; k += 32) {
        float w  = out_w[(size_t)r * H_ + k];
        float wh = __bfloat162float(g_Wout_hi[(size_t)r * H_ + k]);
        float wl = w - wh;
        sh += wh * wh;
        sl += wl * wl;
    }
#pragma unroll
    for (int s = 16; s > 0; s >>= 1) {
        sh += __shfl_xor_sync(0xffffffffu, sh, s);
        sl += __shfl_xor_sync(0xffffffffu, sl, s);
    }
    if (lane == 0) {
        atomicMax(&g_nmax[0], __float_as_uint(sqrtf(sh)));
        atomicMax(&g_nmax[1], __float_as_uint(sqrtf(sl)));
    }
}

// gather embedding + split; reset per-batch norm accumulators
__global__ void k_split_x(const float* __restrict__ emb) {
    int idx = blockIdx.x * blockDim.x + threadIdx.x;
    if (idx < 2 * B_) g_hnorm[idx] = 0.f;
    if (idx >= B_ * E_) return;
    int b = idx >> 9;
    int k = idx & (E_ - 1);
    float v = emb[(size_t)g_inp[b] * E_ + k];
    __nv_bfloat16 h = __float2bfloat16(v);
    g_x_hi[idx] = h;
    g_x_lo[idx] = __float2bfloat16(v - __bfloat162float(h));
}

// GRU gates + h update + split + PER-BATCH norm accumulation
__global__ void __launch_bounds__(256) k_gates2() {
    __shared__ float sb1[B_], sb2[B_];
    int tid = threadIdx.x;
    if (tid < B_) { sb1[tid] = 0.f; sb2[tid] = 0.f; }
    __syncthreads();

    int idx = blockIdx.x * 256 + tid;
    int b = idx & (B_ - 1);
    int i = idx >> 6;
    float ir  = g_giT[(size_t)i * 64 + b];
    float iz  = g_giT[(size_t)(H_ + i) * 64 + b];
    float in_ = g_giT[(size_t)(2 * H_ + i) * 64 + b];
    float hr  = g_ghT[(size_t)i * 64 + b];
    float hz  = g_ghT[(size_t)(H_ + i) * 64 + b];
    float hn  = g_ghT[(size_t)(2 * H_ + i) * 64 + b];
    float r = 1.f / (1.f + expf(-(ir + hr)));
    float z = 1.f / (1.f + expf(-(iz + hz)));
    float n = tanhf(in_ + r * hn);
    size_t hidx = (size_t)b * H_ + i;
    float h = g_h[hidx];
    float hnew = (1.f - z) * n + z * h;
    g_h[hidx] = hnew;
    __nv_bfloat16 hh = __float2bfloat16(hnew);
    g_h_hi[hidx] = hh;
    float hif = __bfloat162float(hh);
    float res = hnew - hif;
    g_h_lo[hidx] = __float2bfloat16(res);

    atomicAdd(&sb1[b], hnew * hnew);
    atomicAdd(&sb2[b], res * res);
    __syncthreads();
    if (tid < B_) {
        atomicAdd(&g_hnorm[tid],      sb1[tid]);
        atomicAdd(&g_hnorm[B_ + tid], sb2[tid]);
    }
}

// ---------------------------------------------------------------------------
// Rescore: per-batch bound, candidate rescore in exact fp32, full-scan fallback.
// ---------------------------------------------------------------------------
__global__ void __launch_bounds__(256) k_rescore(
    const float* __restrict__ out_w, const float* __restrict__ out_b,
    float* __restrict__ out_tok, int t)
{
    __shared__ float sh_h[H_];
    __shared__ int cand[CAND_CAP];
    __shared__ int cnt;
    __shared__ float smax[8];
    __shared__ unsigned long long bestkey;

    const int b = blockIdx.x;
    const int tid = threadIdx.x, lane = tid & 31, warp = tid >> 5;
    const float* ap = g_applog + (size_t)b * V_;

    for (int i = tid; i < H_; i += 256) sh_h[i] = g_h[(size_t)b * H_ + i];
    if (tid == 0) { cnt = 0; bestkey = 0ULL; }
    __syncthreads();

    // pass A: max of approx logits
    float mx = -1e30f;
    for (int r = tid; r < V_; r += 256) mx = fmaxf(mx, ap[r]);
#pragma unroll
    for (int s = 16; s > 0; s >>= 1)
        mx = fmaxf(mx, __shfl_xor_sync(0xffffffffu, mx, s));
    if (lane == 0) smax[warp] = mx;
    __syncthreads();
    if (tid == 0) {
        float m = smax[0];
#pragma unroll
        for (int w = 1; w < 8; w++) m = fmaxf(m, smax[w]);
        smax[0] = m;
    }
    __syncthreads();
    const float A = smax[0];

    // per-batch norms (the R9 bug was using batch-summed norms here)
    const float nh  = sqrtf(g_hnorm[b]);
    const float nhl = sqrtf(g_hnorm[B_ + b]);
    const float nwh = __uint_as_float(g_nmax[0]);
    const float nwl = __uint_as_float(g_nmax[1]);
    const float eps = 2.f * (nwl * nh + nwh * nhl) + 0.1f;
    const float thresh = A - eps;

    // pass B: candidates
    for (int r = tid; r < V_; r += 256) {
        if (ap[r] >= thresh) {
            int i = atomicAdd(&cnt, 1);
            if (i < CAND_CAP) cand[i] = r;
        }
    }
    __syncthreads();

    if (cnt <= CAND_CAP) {
        const int nc = cnt;
        for (int ci = warp; ci < nc; ci += 8) {
            const int r = cand[ci];
            float s = 0.f;
            for (int k = lane; k < H_; k += 32)
                s += out_w[(size_t)r * H_ + k] * sh_h[k];
#pragma unroll
            for (int sft = 16; sft > 0; sft >>= 1)
                s += __shfl_xor_sync(0xffffffffu, s, sft);
            if (lane == 0)
                atomicMax(&bestkey, packkey(s + out_b[r], r));
        }
    } else {
        // overflow: exact full scan — correctness independent of the bound
        for (int r = warp; r < V_; r += 8) {
            float s = 0.f;
            for (int k = lane; k < H_; k += 32)
                s += out_w[(size_t)r * H_ + k] * sh_h[k];
#pragma unroll
            for (int sft = 16; sft > 0; sft >>= 1)
                s += __shfl_xor_sync(0xffffffffu, s, sft);
            if (lane == 0)
                atomicMax(&bestkey, packkey(s + out_b[r], r));
        }
    }
    __syncthreads();

    if (tid == 0) {
        int tok = (int)(0xFFFFFFFFu - (unsigned)(bestkey & 0xFFFFFFFFull));
        out_tok[b * T_ + t] = (float)tok;
        int fin = g_fin[b] | (tok == EOS);
        g_fin[b] = fin;
        g_inp[b] = fin ? EOS : tok;
    }
}

__global__ void k_writeh(float* __restrict__ out_h) {
    int idx = blockIdx.x * blockDim.x + threadIdx.x;
    if (idx < B_ * H_) out_h[idx] = g_h[idx];
}

// ---------------------------------------------------------------------------
extern "C" void kernel_launch(void* const* d_in, const int* in_sizes, int n_in,
                              void* d_out, int out_size) {
    const float* enc   = (const float*)d_in[0];
    const float* emb   = (const float*)d_in[1];
    const float* Wh_w  = (const float*)d_in[2];
    const float* Wh_b  = (const float*)d_in[3];
    const float* W_ih  = (const float*)d_in[4];
    const float* W_hh  = (const float*)d_in[5];
    const float* b_ih  = (const float*)d_in[6];
    const float* b_hh  = (const float*)d_in[7];
    const float* out_w = (const float*)d_in[8];
    const float* out_b = (const float*)d_in[9];
    float* out = (float*)d_out;

    void* pv;
    cudaGetSymbolAddress(&pv, g_flat);     float* f_flat = (float*)pv;
    cudaGetSymbolAddress(&pv, g_h);        float* f_h    = (float*)pv;
    cudaGetSymbolAddress(&pv, g_Gc);       float* f_Gc   = (float*)pv;
    cudaGetSymbolAddress(&pv, g_WihE_hi);  __nv_bfloat16* w_ihe_h = (__nv_bfloat16*)pv;
    cudaGetSymbolAddress(&pv, g_WihE_lo);  __nv_bfloat16* w_ihe_l = (__nv_bfloat16*)pv;
    cudaGetSymbolAddress(&pv, g_Whh_hi);   __nv_bfloat16* w_hh_h  = (__nv_bfloat16*)pv;
    cudaGetSymbolAddress(&pv, g_Whh_lo);   __nv_bfloat16* w_hh_l  = (__nv_bfloat16*)pv;
    cudaGetSymbolAddress(&pv, g_Wout_hi);  __nv_bfloat16* w_o_h   = (__nv_bfloat16*)pv;

    cudaFuncSetAttribute(k_tc_gates,  cudaFuncAttributeMaxDynamicSharedMemorySize, TCSMEM2);
    cudaFuncSetAttribute(k_tc_logits, cudaFuncAttributeMaxDynamicSharedMemorySize, TCSMEM1);

    // ---- one-time setup ----
    k_setup<<<256, 256>>>(enc);
    k_gemm<<<H_ / 64, 256>>>(f_flat, 2 * HENC, Wh_w, 2 * HENC, 0, 2 * HENC, Wh_b, f_h, H_);
    k_gemm<<<3 * H_ / 64, 256>>>(f_flat, 2 * HENC, W_ih, E_ + 2 * HENC, E_, 2 * HENC,
                                 b_ih, f_Gc, 3 * H_);
    k_split_h0<<<(B_ * H_) / 256, 256>>>();
    k_mk_gcT<<<(3 * H_ * B_) / 256, 256>>>();
    k_splitw<<<(3 * H_ * E_) / 256, 256>>>(W_ih, E_ + 2 * HENC, 0, E_,
                                           w_ihe_h, w_ihe_l, 3 * H_ * E_);
    k_splitw<<<(3 * H_ * H_) / 256, 256>>>(W_hh, H_, 0, H_,
                                           w_hh_h, w_hh_l, 3 * H_ * H_);
    k_splitw<<<(V_ * H_) / 256, 256>>>(out_w, H_, 0, H_,
                                       w_o_h, nullptr, V_ * H_);
    k_wnorms<<<V_ / 8, 256>>>(out_w);

    // ---- decode loop ----
    dim3 ggates(3 * H_ / 128, 2);
    for (int t = 0; t < T_; t++) {
        k_split_x<<<(B_ * E_) / 256, 256>>>(emb);
        k_tc_gates<<<ggates, 256, TCSMEM2>>>(b_hh);
        k_gates2<<<(B_ * H_) / 256, 256>>>();
        k_tc_logits<<<V_ / 128, 256, TCSMEM1>>>(out_b);
        k_rescore<<<B_, 256>>>(out_w, out_b, out, t);
    }

    if (out_size >= B_ * T_ + B_ * H_)
        k_writeh<<<(B_ * H_) / 256, 256>>>(out + B_ * T_);
}